// round 14
// baseline (speedup 1.0000x reference)
#include <cuda_runtime.h>
#include <cuda_fp16.h>

// ---------------- problem constants ----------------
#define C_CLASSES 8192
#define B_ROWS    256
#define N_ROWS    1280           // B + M*B
#define MAXP      64             // per-class positive cap

#define NI        (B_ROWS * C_CLASSES)   // 2097152 interclass elements
#define LG_BINS   18
#define BINS      (1 << LG_BINS)         // 262144
#define KEY_SHIFT (32 - LG_BINS)         // 14
#define CHUNK     32
#define NCHUNK    (BINS / CHUNK)         // 8192
#define MAXPOS    65536
#define NPWORDS   (NI / 32)              // 65536 posbit words
#define KPA_BLOCKS 32                    // bins per kpa block: 256*32 = 8192

// ---------------- scratch (device globals; no allocation allowed) ----------------
__device__ __half   g_tsT[(size_t)C_CLASSES * N_ROWS];  // fp16 perturbed scores (class-major)
__device__ float    g_cpos[(size_t)C_CLASSES * MAXP];   // per-class positive values (fp32)
__device__ int      g_pcnt[C_CLASSES];                  // per-class positive counts
__device__ float    g_prec[C_CLASSES];
__device__ int      g_present[C_CLASSES];

__device__ unsigned g_ikeys[NI];          // interclass order-keys
__device__ unsigned g_iposbit[NPWORDS];   // interclass positive bitmask
__device__ int      g_phist[BINS];        // positive count per bin
__device__ int      g_pexcl[BINS];        // exclusive prefix of g_phist
__device__ int      g_pcursor[BINS];
__device__ int      g_pchunksum[NCHUNK];
__device__ unsigned g_pkeys[MAXPOS];      // positive keys grouped by bin
__device__ int      g_gapneg[MAXPOS + 64];
__device__ int      g_mtotal;
__device__ int      g_kpa_done;

// ---------------- RNG: murmur3 finalizer -> popc-normal (cheap, no MUFU) ----------------
__device__ __forceinline__ float abs_normal(unsigned idx) {
    unsigned h = idx * 0x9E3779B1u;
    h ^= h >> 16; h *= 0x85EBCA6Bu;
    h ^= h >> 13; h *= 0xC2B2AE35u;
    h ^= h >> 16;
    unsigned h2 = h * 0x2545F491u;                              // decorrelate jitter
    float b = (float)(__popc(h) - 16);
    float u = fmaf((float)(h2 >> 8), 5.9604645e-08f, -0.5f);    // [-0.5, 0.5)
    return fabsf((b + u) * 0.35172433f);                         // 1/sqrt(8+1/12)
}

__device__ __forceinline__ unsigned order_key(float v) {
    unsigned u = __float_as_uint(v);
    return (u & 0x80000000u) ? ~u : (u | 0x80000000u);
}

__device__ __forceinline__ int warp_sum(int v) {
    #pragma unroll
    for (int off = 16; off; off >>= 1) v += __shfl_xor_sync(0xffffffffu, v, off);
    return v;
}

__device__ __forceinline__ half2 warp_sum_h2(half2 v) {
    #pragma unroll
    for (int off = 16; off; off >>= 1) {
        unsigned u = __shfl_xor_sync(0xffffffffu, *(unsigned*)&v, off);
        v = __hadd2(v, *(half2*)&u);
    }
    return v;
}

// ---------------- K0: zero counters (vectorized) ----------------
__global__ __launch_bounds__(256) void k0_zero() {
    int i = blockIdx.x * 256 + threadIdx.x;        // 0..65535
    int4 z = make_int4(0, 0, 0, 0);
    ((int4*)g_phist)[i] = z;                        // BINS/4 = 65536
    if (i < (MAXPOS + 64) / 4) ((int4*)g_gapneg)[i] = z;
    if (i < C_CLASSES / 4)     ((int4*)g_pcnt)[i]   = z;
    if (i == 0) g_kpa_done = 0;
}

// ---------------- K1: fused perturb+transpose + interclass keys + positive append ----------------
__global__ __launch_bounds__(256) void k1_fused(
    const float* __restrict__ outp, const float* __restrict__ tgt,
    const float* __restrict__ soutp, const float* __restrict__ stgt)
{
    __shared__ float ts_tile[32][33];

    int tx = threadIdx.x;
    int ty = threadIdx.y;
    int c0 = blockIdx.x * 32;
    int r0 = blockIdx.y * 32;
    int cg = c0 + tx;

    #pragma unroll
    for (int j = 0; j < 4; j++) {
        int rl = ty + 8 * j;
        int row = r0 + rl;
        float sc, t;
        if (row < B_ROWS) {
            size_t o = (size_t)row * C_CLASSES + cg;
            sc = outp[o]; t = tgt[o];
        } else {
            size_t o = (size_t)(row - B_ROWS) * C_CLASSES + cg;
            sc = soutp[o]; t = stgt[o];
        }
        unsigned gi = (unsigned)(row * C_CLASSES + cg);
        float an = abs_normal(gi);
        bool pos = (t > 0.5f);
        float v = pos ? (sc - 0.01f * an) : (sc + 0.01f * an);
        ts_tile[rl][tx] = v;

        if (pos) {
            int d = atomicAdd(&g_pcnt[cg], 1);
            if (d < MAXP) g_cpos[(size_t)cg * MAXP + d] = v;
        }

        if (row < B_ROWS) {   // interclass stream: reuse the SAME perturbed value
            unsigned key = order_key(v);
            g_ikeys[row * C_CLASSES + cg] = key;
            unsigned pb = __ballot_sync(0xffffffffu, pos);
            if (tx == 0) g_iposbit[row * (C_CLASSES / 32) + blockIdx.x] = pb;
            if (pos) atomicAdd(&g_phist[key >> KEY_SHIFT], 1);
        }
    }
    __syncthreads();

    #pragma unroll
    for (int rep = 0; rep < 4; rep++) {
        int cl  = ty + 8 * rep;
        int cgg = c0 + cl;
        g_tsT[(size_t)cgg * N_ROWS + r0 + tx] = __float2half(ts_tile[tx][cl]);
    }
}

// ---------------- K2X: kpa+kpb (blocks 0..31) and k2 ranking (blocks 32..1055) ----------------
__global__ __launch_bounds__(256) void k2x_rank()
{
    __shared__ int sh[256 * 33];     // 33.8KB: kpa staging; k2 overlays s_pos
    __shared__ int wt[8];
    __shared__ int lastf;

    if (blockIdx.x < KPA_BLOCKS) {
        // ---- kpa: coalesced chunk sums over 8192 bins ----
        int t = threadIdx.x;
        int base_bin = blockIdx.x * 8192;
        #pragma unroll 4
        for (int i = t; i < 8192; i += 256) {
            int c = i >> 5, j = i & 31;
            sh[c * 33 + j] = g_phist[base_bin + i];
        }
        __syncthreads();
        int s = 0;
        #pragma unroll
        for (int j = 0; j < CHUNK; j++) s += sh[t * 33 + j];
        g_pchunksum[blockIdx.x * 256 + t] = s;
        __threadfence();
        if (t == 0) lastf = (atomicAdd(&g_kpa_done, 1) == KPA_BLOCKS - 1) ? 1 : 0;
        __syncthreads();
        if (!lastf) return;
        __threadfence();

        // ---- kpb (last block): exclusive scan over 8192 chunk sums ----
        __syncthreads();
        #pragma unroll 4
        for (int i = t; i < NCHUNK; i += 256) {
            int c = i >> 5, j = i & 31;
            sh[c * 33 + j] = g_pchunksum[i];
        }
        __syncthreads();
        int loc[CHUNK];
        int lsum = 0;
        #pragma unroll
        for (int j = 0; j < CHUNK; j++) { loc[j] = sh[t * 33 + j]; lsum += loc[j]; }
        int lane = t & 31, wid = t >> 5;
        int si = lsum;
        #pragma unroll
        for (int off = 1; off < 32; off <<= 1) {
            int n = __shfl_up_sync(0xffffffffu, si, off);
            if (lane >= off) si += n;
        }
        if (lane == 31) wt[wid] = si;
        __syncthreads();
        if (wid == 0 && lane < 8) {
            int w = wt[lane];
            #pragma unroll
            for (int off = 1; off < 8; off <<= 1) {
                int n = __shfl_up_sync(0xffu, w, off);
                if (lane >= off) w += n;
            }
            wt[lane] = w;
        }
        __syncthreads();
        int run = (wid > 0 ? wt[wid - 1] : 0) + si - lsum;
        #pragma unroll
        for (int j = 0; j < CHUNK; j++) { sh[t * 33 + j] = run; run += loc[j]; }
        if (t == 255) g_mtotal = run;
        __syncthreads();
        #pragma unroll 4
        for (int i = t; i < NCHUNK; i += 256) {
            int c = i >> 5, j = i & 31;
            g_pchunksum[i] = sh[c * 33 + j];
        }
        return;
    }

    // ---- k2: per-class ranking, counters-then-reduce ----
    float* s_pos = (float*)sh;                 // [8][64] floats = 2KB
    int lane = threadIdx.x & 31;
    int wid  = threadIdx.x >> 5;
    int c    = (blockIdx.x - KPA_BLOCKS) * 8 + wid;

    const uint4* rowp = (const uint4*)(g_tsT + (size_t)c * N_ROWS);
    uint4 v[5];
    #pragma unroll
    for (int i = 0; i < 5; i++) v[i] = rowp[i * 32 + lane];

    int m = g_pcnt[c];
    int ms = (m < MAXP) ? m : MAXP;
    for (int i = lane; i < ms; i += 32)
        s_pos[wid * MAXP + i] = g_cpos[(size_t)c * MAXP + i];
    if (lane == 0 && (ms & 1)) s_pos[wid * MAXP + ms] = 1e30f;   // pad odd
    __syncwarp();

    // positive pairs in registers (unused pairs -> +inf: hgt2 yields 0)
    int npairs = (ms + 1) >> 1;
    half2 p2[8];
    #pragma unroll
    for (int q = 0; q < 8; q++) {
        if (q < npairs)
            p2[q] = __floats2half2_rn(s_pos[wid * MAXP + 2 * q], s_pos[wid * MAXP + 2 * q + 1]);
        else
            p2[q] = __floats2half2_rn(1e30f, 1e30f);
    }

    half2 cnt[8];
    #pragma unroll
    for (int q = 0; q < 8; q++) cnt[q] = __half2half2(__ushort_as_half(0));

    #pragma unroll
    for (int i = 0; i < 5; i++) {
        const unsigned* w = &v[i].x;
        #pragma unroll
        for (int k = 0; k < 4; k++) {
            half2 h  = *(const half2*)&w[k];
            half2 vl = __low2half2(h);
            half2 vh = __high2half2(h);
            #pragma unroll
            for (int q = 0; q < 8; q++) {
                cnt[q] = __hadd2(cnt[q], __hgt2(vl, p2[q]));
                cnt[q] = __hadd2(cnt[q], __hgt2(vh, p2[q]));
            }
        }
    }
    // independent warp reductions (pipelined shfl chains)
    #pragma unroll
    for (int q = 0; q < 8; q++) cnt[q] = warp_sum_h2(cnt[q]);

    float sum = 0.0f;
    for (int kk = 0; kk < ms; kk++) {
        float p = s_pos[wid * MAXP + kk];
        half2 cq = cnt[0];
        #pragma unroll
        for (int q = 1; q < 8; q++) if ((kk >> 1) == q) cq = cnt[q];
        float cf = (kk & 1) ? __high2float(cq) : __low2float(cq);
        float r = cf + 1.0f;
        int s = 1;
        for (int jj = 0; jj < ms; jj++) s += (s_pos[wid * MAXP + jj] > p);
        sum += (float)s / r;
    }
    if (lane == 0) {
        g_prec[c]    = sum / ((float)m + 1e-5f);
        g_present[c] = (m > 0) ? 1 : 0;
    }
}

// ---------------- KPC: coalesced per-bin offsets via smem staging ----------------
__global__ __launch_bounds__(256) void kpc_offsets() {
    __shared__ int sh[256 * 33];
    int t = threadIdx.x;
    int base_bin = blockIdx.x * 8192;
    #pragma unroll 4
    for (int i = t; i < 8192; i += 256) {
        int c = i >> 5, j = i & 31;
        sh[c * 33 + j] = g_phist[base_bin + i];
    }
    __syncthreads();
    int run = g_pchunksum[blockIdx.x * 256 + t];
    #pragma unroll
    for (int j = 0; j < CHUNK; j++) {
        int h = sh[t * 33 + j];
        sh[t * 33 + j] = run;
        run += h;
    }
    __syncthreads();
    #pragma unroll 4
    for (int i = t; i < 8192; i += 256) {
        int c = i >> 5, j = i & 31;
        int e = sh[c * 33 + j];
        g_pexcl[base_bin + i]   = e;
        g_pcursor[base_bin + i] = e;
    }
}

// ---------------- scatter positive keys by bin ----------------
__global__ __launch_bounds__(256) void kps_scatter() {
    int w = blockIdx.x * 256 + threadIdx.x;   // 0..NPWORDS-1
    unsigned bits = g_iposbit[w];
    while (bits) {
        int bit = __ffs(bits) - 1;
        bits &= (bits - 1);
        int i = w * 32 + bit;
        unsigned key = g_ikeys[i];
        int b = key >> KEY_SHIFT;
        int d = atomicAdd(&g_pcursor[b], 1);
        g_pkeys[d] = key;
    }
}

// ---------------- KC: per-element gap counting (8-way ILP) ----------------
#define KC_ILP 8
#define KC_THREADS (NI / KC_ILP)   // 262144
__global__ __launch_bounds__(256) void kc_gaps() {
    int tid = blockIdx.x * 256 + threadIdx.x;
    int m = g_mtotal;

    unsigned key[KC_ILP]; unsigned pb[KC_ILP];
    int e0[KC_ILP], pc[KC_ILP];
    #pragma unroll
    for (int u = 0; u < KC_ILP; u++) {
        int i = tid + u * KC_THREADS;
        key[u] = g_ikeys[i];
        pb[u]  = g_iposbit[i >> 5];       // broadcast within warp
    }
    #pragma unroll
    for (int u = 0; u < KC_ILP; u++) {
        int b = key[u] >> KEY_SHIFT;
        e0[u] = g_pexcl[b];
        pc[u] = g_phist[b];
    }
    #pragma unroll
    for (int u = 0; u < KC_ILP; u++) {
        int i = tid + u * KC_THREADS;
        int cgt = 0;
        for (int t = 0; t < pc[u]; t++) cgt += (g_pkeys[e0[u] + t] > key[u]);
        int j = (m - e0[u] - pc[u]) + cgt;   // # positives > this element
        bool pos = (pb[u] >> (i & 31)) & 1u;
        if (!pos) atomicAdd(&g_gapneg[j], 1);
    }
}

// ---------------- KS3: gap scan + interclass terms + final combine ----------------
__global__ __launch_bounds__(1024) void ks3_final(float* __restrict__ out, int out_size)
{
    __shared__ int wtot[32];
    __shared__ double wsumd[32];
    __shared__ int wsumi[32];
    int t = threadIdx.x;
    int lane = t & 31, wid = t >> 5;
    int m = g_mtotal;

    int carry = 0;
    double acc = 0.0;
    for (int base = 0; base < m; base += 1024) {
        int i = base + t;
        int g = (i < m) ? g_gapneg[i] : 0;
        int si = g;
        #pragma unroll
        for (int off = 1; off < 32; off <<= 1) {
            int n = __shfl_up_sync(0xffffffffu, si, off);
            if (lane >= off) si += n;
        }
        if (lane == 31) wtot[wid] = si;
        __syncthreads();
        if (wid == 0) {
            int w = wtot[lane];
            #pragma unroll
            for (int off = 1; off < 32; off <<= 1) {
                int n = __shfl_up_sync(0xffffffffu, w, off);
                if (lane >= off) w += n;
            }
            wtot[lane] = w;
        }
        __syncthreads();
        int P = (wid > 0 ? wtot[wid - 1] : 0) + si;
        if (i < m) {
            int r = 1 + i + carry + P;
            acc += (double)(i + 1) / (double)r;
        }
        carry += wtot[31];
        __syncthreads();
    }
    #pragma unroll
    for (int off = 16; off; off >>= 1) acc += __shfl_xor_sync(0xffffffffu, acc, off);
    if (lane == 0) wsumd[wid] = acc;
    __syncthreads();
    double isum = 0.0;
    if (t == 0) {
        #pragma unroll
        for (int i = 0; i < 32; i++) isum += wsumd[i];
    }
    __syncthreads();

    double ps = 0.0; int pr = 0;
    for (int i = t; i < C_CLASSES; i += 1024) { ps += (double)g_prec[i]; pr += g_present[i]; }
    #pragma unroll
    for (int off = 16; off; off >>= 1) {
        ps += __shfl_xor_sync(0xffffffffu, ps, off);
        pr += __shfl_xor_sync(0xffffffffu, pr, off);
    }
    if (lane == 0) { wsumd[wid] = ps; wsumi[wid] = pr; }
    __syncthreads();
    if (t == 0) {
        double pst = 0.0; int prt = 0;
        #pragma unroll
        for (int i = 0; i < 32; i++) { pst += wsumd[i]; prt += wsumi[i]; }
        int denom = (prt > 0) ? prt : 1;
        float cross = 1.0f - (float)(pst / (double)denom);
        float inter = (m > 0) ? (1.0f - (float)(isum / ((double)m + 1e-5))) : 1.0f;
        float loss = 0.5f * cross + 0.5f * inter;
        for (int j = 0; j < out_size; j++) out[j] = loss;
    }
}

// ---------------- launch ----------------
extern "C" void kernel_launch(void* const* d_in, const int* in_sizes, int n_in,
                              void* d_out, int out_size)
{
    const int SMALL = B_ROWS * C_CLASSES;
    const float* small_p[2] = {nullptr, nullptr};
    const float* big_p[2]   = {nullptr, nullptr};
    int ns = 0, nb = 0;
    for (int i = 0; i < n_in; i++) {
        if (in_sizes[i] == SMALL) { if (ns < 2) small_p[ns++] = (const float*)d_in[i]; }
        else                      { if (nb < 2) big_p[nb++]   = (const float*)d_in[i]; }
    }
    const float* outp  = small_p[0];
    const float* tgt   = small_p[1];
    const float* soutp = big_p[0];
    const float* stgt  = big_p[1];

    k0_zero<<<(BINS / 4) / 256, 256>>>();                 // #1

    dim3 b1(32, 8);
    dim3 g1(C_CLASSES / 32, N_ROWS / 32);
    k1_fused<<<g1, b1>>>(outp, tgt, soutp, stgt);         // #2

    k2x_rank<<<KPA_BLOCKS + C_CLASSES / 8, 256>>>();      // #3 (kpa+kpb+k2)
    kpc_offsets<<<BINS / 8192, 256>>>();                  // #4  <- profiled launch
    kps_scatter<<<NPWORDS / 256, 256>>>();                // #5
    kc_gaps<<<NI / KC_ILP / 256, 256>>>();                // #6

    ks3_final<<<1, 1024>>>((float*)d_out, out_size);      // #7
}

// round 15
// speedup vs baseline: 1.0257x; 1.0257x over previous
#include <cuda_runtime.h>
#include <cuda_fp16.h>

// ---------------- problem constants ----------------
#define C_CLASSES 8192
#define B_ROWS    256
#define N_ROWS    1280           // B + M*B
#define MAXP      64             // per-class positive cap

#define NI        (B_ROWS * C_CLASSES)   // 2097152 interclass elements
#define LG_BINS   18
#define BINS      (1 << LG_BINS)         // 262144
#define KEY_SHIFT (32 - LG_BINS)         // 14
#define CHUNK     64
#define NCHUNK    (BINS / CHUNK)         // 4096
#define MAXPOS    65536
#define NPWORDS   (NI / 32)              // 65536 posbit words
#define KP_BLOCKS 32
#define KP_T      128                    // threads per kp_all block

// ---------------- scratch (device globals; no allocation allowed) ----------------
__device__ __half   g_tsT[(size_t)C_CLASSES * N_ROWS];  // fp16 perturbed scores (class-major)
__device__ float    g_cpos[(size_t)C_CLASSES * MAXP];   // per-class positive values (fp32)
__device__ int      g_pcnt[C_CLASSES];                  // per-class positive counts
__device__ float    g_prec[C_CLASSES];
__device__ int      g_present[C_CLASSES];

__device__ unsigned g_ikeys[NI];          // interclass order-keys
__device__ unsigned g_iposbit[NPWORDS];   // interclass positive bitmask
__device__ int      g_phist[BINS];        // positive count per bin
__device__ int      g_pexcl[BINS];        // exclusive prefix of g_phist
__device__ int      g_pcursor[BINS];
__device__ int      g_pchunksum[NCHUNK];
__device__ unsigned g_pkeys[MAXPOS];      // positive keys grouped by bin
__device__ int      g_gapneg[MAXPOS + 64];
__device__ int      g_mtotal;
__device__ volatile int g_kp_done;

// ---------------- RNG: murmur3 finalizer -> popc-normal (cheap, no MUFU) ----------------
__device__ __forceinline__ float abs_normal(unsigned idx) {
    unsigned h = idx * 0x9E3779B1u;
    h ^= h >> 16; h *= 0x85EBCA6Bu;
    h ^= h >> 13; h *= 0xC2B2AE35u;
    h ^= h >> 16;
    unsigned h2 = h * 0x2545F491u;                              // decorrelate jitter
    float b = (float)(__popc(h) - 16);
    float u = fmaf((float)(h2 >> 8), 5.9604645e-08f, -0.5f);    // [-0.5, 0.5)
    return fabsf((b + u) * 0.35172433f);                         // 1/sqrt(8+1/12)
}

__device__ __forceinline__ unsigned order_key(float v) {
    unsigned u = __float_as_uint(v);
    return (u & 0x80000000u) ? ~u : (u | 0x80000000u);
}

__device__ __forceinline__ int warp_sum(int v) {
    #pragma unroll
    for (int off = 16; off; off >>= 1) v += __shfl_xor_sync(0xffffffffu, v, off);
    return v;
}
__device__ __forceinline__ float warp_sum_f(float v) {
    #pragma unroll
    for (int off = 16; off; off >>= 1) v += __shfl_xor_sync(0xffffffffu, v, off);
    return v;
}

// ---------------- K0: zero counters (vectorized) ----------------
__global__ __launch_bounds__(256) void k0_zero() {
    int i = blockIdx.x * 256 + threadIdx.x;        // 0..65535
    int4 z = make_int4(0, 0, 0, 0);
    ((int4*)g_phist)[i] = z;                        // BINS/4 = 65536
    if (i < (MAXPOS + 64) / 4) ((int4*)g_gapneg)[i] = z;
    if (i < C_CLASSES / 4)     ((int4*)g_pcnt)[i]   = z;
    if (i == 0) g_kp_done = 0;
}

// ---------------- K1: fused perturb+transpose + interclass keys + positive append ----------------
__global__ __launch_bounds__(256) void k1_fused(
    const float* __restrict__ outp, const float* __restrict__ tgt,
    const float* __restrict__ soutp, const float* __restrict__ stgt)
{
    __shared__ float ts_tile[32][33];

    int tx = threadIdx.x;
    int ty = threadIdx.y;
    int c0 = blockIdx.x * 32;
    int r0 = blockIdx.y * 32;
    int cg = c0 + tx;

    #pragma unroll
    for (int j = 0; j < 4; j++) {
        int rl = ty + 8 * j;
        int row = r0 + rl;
        float sc, t;
        if (row < B_ROWS) {
            size_t o = (size_t)row * C_CLASSES + cg;
            sc = outp[o]; t = tgt[o];
        } else {
            size_t o = (size_t)(row - B_ROWS) * C_CLASSES + cg;
            sc = soutp[o]; t = stgt[o];
        }
        unsigned gi = (unsigned)(row * C_CLASSES + cg);
        float an = abs_normal(gi);
        bool pos = (t > 0.5f);
        float v = pos ? (sc - 0.01f * an) : (sc + 0.01f * an);
        ts_tile[rl][tx] = v;

        if (pos) {
            int d = atomicAdd(&g_pcnt[cg], 1);
            if (d < MAXP) g_cpos[(size_t)cg * MAXP + d] = v;
        }

        if (row < B_ROWS) {   // interclass stream: reuse the SAME perturbed value
            unsigned key = order_key(v);
            g_ikeys[row * C_CLASSES + cg] = key;
            unsigned pb = __ballot_sync(0xffffffffu, pos);
            if (tx == 0) g_iposbit[row * (C_CLASSES / 32) + blockIdx.x] = pb;
            if (pos) atomicAdd(&g_phist[key >> KEY_SHIFT], 1);
        }
    }
    __syncthreads();

    #pragma unroll
    for (int rep = 0; rep < 4; rep++) {
        int cl  = ty + 8 * rep;
        int cgg = c0 + cl;
        g_tsT[(size_t)cgg * N_ROWS + r0 + tx] = __float2half(ts_tile[tx][cl]);
    }
}

// ---------------- K2: per-class ranking with packed fp16 compares (R13-proven) ----------------
__global__ __launch_bounds__(256) void k2_rank()
{
    __shared__ float s_pos[8][MAXP];
    int lane = threadIdx.x & 31;
    int wid  = threadIdx.x >> 5;
    int c    = blockIdx.x * 8 + wid;

    const uint4* rowp = (const uint4*)(g_tsT + (size_t)c * N_ROWS);
    uint4 v[5];
    #pragma unroll
    for (int i = 0; i < 5; i++) v[i] = rowp[i * 32 + lane];

    int m = g_pcnt[c];
    int ms = (m < MAXP) ? m : MAXP;
    for (int i = lane; i < ms; i += 32)
        s_pos[wid][i] = g_cpos[(size_t)c * MAXP + i];
    __syncwarp();

    float sum = 0.0f;
    for (int kk = 0; kk < ms; kk++) {
        float p = s_pos[wid][kk];
        half2 p2 = __half2half2(__float2half(p));
        half2 c2 = __half2half2(__ushort_as_half(0));
        #pragma unroll
        for (int i = 0; i < 5; i++) {
            c2 = __hadd2(c2, __hgt2(*(const half2*)&v[i].x, p2));
            c2 = __hadd2(c2, __hgt2(*(const half2*)&v[i].y, p2));
            c2 = __hadd2(c2, __hgt2(*(const half2*)&v[i].z, p2));
            c2 = __hadd2(c2, __hgt2(*(const half2*)&v[i].w, p2));
        }
        float cnt = __low2float(c2) + __high2float(c2);
        float r = warp_sum_f(cnt) + 1.0f;
        int s = 1;
        for (int jj = 0; jj < ms; jj++) s += (s_pos[wid][jj] > p);
        sum += (float)s / r;
    }
    if (lane == 0) {
        g_prec[c]    = sum / ((float)m + 1e-5f);
        g_present[c] = (m > 0) ? 1 : 0;
    }
}

// ---------------- KP_ALL: fused chunk-sum + scan + per-bin offsets (32 resident blocks) ----------------
__global__ __launch_bounds__(KP_T) void kp_all() {
    __shared__ int sh[KP_T * 65];     // bin staging: 128 chunks x 64 bins (+pad) = 33.3KB
    __shared__ int cs[NCHUNK];        // all chunk sums: 16KB
    __shared__ int wt[4];

    int t = threadIdx.x;
    int lane = t & 31, wid = t >> 5;
    int base_bin = blockIdx.x * KP_T * CHUNK;      // 8192 bins per block

    // ---- Phase A: coalesced load of this block's bins; chunk sums ----
    #pragma unroll 8
    for (int i = t; i < KP_T * CHUNK; i += KP_T) {
        int c = i >> 6, j = i & 63;
        sh[c * 65 + j] = g_phist[base_bin + i];
    }
    __syncthreads();
    int s = 0;
    #pragma unroll 16
    for (int j = 0; j < CHUNK; j++) s += sh[t * 65 + j];
    g_pchunksum[blockIdx.x * KP_T + t] = s;
    __threadfence();
    __syncthreads();
    if (t == 0) atomicAdd((int*)&g_kp_done, 1);

    // ---- grid barrier: all 32 blocks resident (32 << 148 SMs) ----
    if (t == 0) { while (g_kp_done < KP_BLOCKS) { } }
    __syncthreads();
    __threadfence();

    // ---- Phase B: every block scans all 4096 chunk sums (redundant, deterministic) ----
    #pragma unroll 8
    for (int i = t; i < NCHUNK; i += KP_T) cs[i] = g_pchunksum[i];
    __syncthreads();
    // thread t owns chunks [t*32, t*32+32)
    int loc = 0;
    #pragma unroll 8
    for (int j = 0; j < 32; j++) loc += cs[t * 32 + j];
    int si = loc;
    #pragma unroll
    for (int off = 1; off < 32; off <<= 1) {
        int n = __shfl_up_sync(0xffffffffu, si, off);
        if (lane >= off) si += n;
    }
    if (lane == 31) wt[wid] = si;
    __syncthreads();
    int wbase = 0;
    #pragma unroll
    for (int q = 0; q < 4; q++) if (q < wid) wbase += wt[q];
    int run0 = wbase + si - loc;                   // exclusive prefix at chunk t*32
    if (t == KP_T - 1) g_mtotal = wbase + si;       // total positives
    // in-place exclusive scan of this thread's 32 chunks
    int run = run0;
    #pragma unroll 8
    for (int j = 0; j < 32; j++) { int h = cs[t * 32 + j]; cs[t * 32 + j] = run; run += h; }
    __syncthreads();

    // ---- Phase C: per-bin exclusive offsets for this block's region ----
    int crun = cs[blockIdx.x * KP_T + t];           // scanned chunk sum for this thread's chunk
    #pragma unroll 16
    for (int j = 0; j < CHUNK; j++) {
        int h = sh[t * 65 + j];
        sh[t * 65 + j] = crun;
        crun += h;
    }
    __syncthreads();
    #pragma unroll 8
    for (int i = t; i < KP_T * CHUNK; i += KP_T) {
        int c = i >> 6, j = i & 63;
        int e = sh[c * 65 + j];
        g_pexcl[base_bin + i]   = e;                // coalesced writes
        g_pcursor[base_bin + i] = e;
    }
}

// ---------------- scatter positive keys by bin ----------------
__global__ __launch_bounds__(256) void kps_scatter() {
    int w = blockIdx.x * 256 + threadIdx.x;   // 0..NPWORDS-1
    unsigned bits = g_iposbit[w];
    while (bits) {
        int bit = __ffs(bits) - 1;
        bits &= (bits - 1);
        int i = w * 32 + bit;
        unsigned key = g_ikeys[i];
        int b = key >> KEY_SHIFT;
        int d = atomicAdd(&g_pcursor[b], 1);
        g_pkeys[d] = key;
    }
}

// ---------------- KC: per-element gap counting (8-way ILP) ----------------
#define KC_ILP 8
#define KC_THREADS (NI / KC_ILP)   // 262144
__global__ __launch_bounds__(256) void kc_gaps() {
    int tid = blockIdx.x * 256 + threadIdx.x;
    int m = g_mtotal;

    unsigned key[KC_ILP]; unsigned pb[KC_ILP];
    int e0[KC_ILP], pc[KC_ILP];
    #pragma unroll
    for (int u = 0; u < KC_ILP; u++) {
        int i = tid + u * KC_THREADS;
        key[u] = g_ikeys[i];
        pb[u]  = g_iposbit[i >> 5];       // broadcast within warp
    }
    #pragma unroll
    for (int u = 0; u < KC_ILP; u++) {
        int b = key[u] >> KEY_SHIFT;
        e0[u] = g_pexcl[b];
        pc[u] = g_phist[b];
    }
    #pragma unroll
    for (int u = 0; u < KC_ILP; u++) {
        int i = tid + u * KC_THREADS;
        int cgt = 0;
        for (int t = 0; t < pc[u]; t++) cgt += (g_pkeys[e0[u] + t] > key[u]);
        int j = (m - e0[u] - pc[u]) + cgt;   // # positives > this element
        bool pos = (pb[u] >> (i & 31)) & 1u;
        if (!pos) atomicAdd(&g_gapneg[j], 1);
    }
}

// ---------------- KS3: gap scan + interclass terms + final combine ----------------
__global__ __launch_bounds__(1024) void ks3_final(float* __restrict__ out, int out_size)
{
    __shared__ int wtot[32];
    __shared__ double wsumd[32];
    __shared__ int wsumi[32];
    int t = threadIdx.x;
    int lane = t & 31, wid = t >> 5;
    int m = g_mtotal;

    int carry = 0;
    double acc = 0.0;
    for (int base = 0; base < m; base += 1024) {
        int i = base + t;
        int g = (i < m) ? g_gapneg[i] : 0;
        int si = g;
        #pragma unroll
        for (int off = 1; off < 32; off <<= 1) {
            int n = __shfl_up_sync(0xffffffffu, si, off);
            if (lane >= off) si += n;
        }
        if (lane == 31) wtot[wid] = si;
        __syncthreads();
        if (wid == 0) {
            int w = wtot[lane];
            #pragma unroll
            for (int off = 1; off < 32; off <<= 1) {
                int n = __shfl_up_sync(0xffffffffu, w, off);
                if (lane >= off) w += n;
            }
            wtot[lane] = w;
        }
        __syncthreads();
        int P = (wid > 0 ? wtot[wid - 1] : 0) + si;
        if (i < m) {
            int r = 1 + i + carry + P;
            acc += (double)(i + 1) / (double)r;
        }
        carry += wtot[31];
        __syncthreads();
    }
    #pragma unroll
    for (int off = 16; off; off >>= 1) acc += __shfl_xor_sync(0xffffffffu, acc, off);
    if (lane == 0) wsumd[wid] = acc;
    __syncthreads();
    double isum = 0.0;
    if (t == 0) {
        #pragma unroll
        for (int i = 0; i < 32; i++) isum += wsumd[i];
    }
    __syncthreads();

    double ps = 0.0; int pr = 0;
    for (int i = t; i < C_CLASSES; i += 1024) { ps += (double)g_prec[i]; pr += g_present[i]; }
    #pragma unroll
    for (int off = 16; off; off >>= 1) {
        ps += __shfl_xor_sync(0xffffffffu, ps, off);
        pr += __shfl_xor_sync(0xffffffffu, pr, off);
    }
    if (lane == 0) { wsumd[wid] = ps; wsumi[wid] = pr; }
    __syncthreads();
    if (t == 0) {
        double pst = 0.0; int prt = 0;
        #pragma unroll
        for (int i = 0; i < 32; i++) { pst += wsumd[i]; prt += wsumi[i]; }
        int denom = (prt > 0) ? prt : 1;
        float cross = 1.0f - (float)(pst / (double)denom);
        float inter = (m > 0) ? (1.0f - (float)(isum / ((double)m + 1e-5))) : 1.0f;
        float loss = 0.5f * cross + 0.5f * inter;
        for (int j = 0; j < out_size; j++) out[j] = loss;
    }
}

// ---------------- launch ----------------
extern "C" void kernel_launch(void* const* d_in, const int* in_sizes, int n_in,
                              void* d_out, int out_size)
{
    const int SMALL = B_ROWS * C_CLASSES;
    const float* small_p[2] = {nullptr, nullptr};
    const float* big_p[2]   = {nullptr, nullptr};
    int ns = 0, nb = 0;
    for (int i = 0; i < n_in; i++) {
        if (in_sizes[i] == SMALL) { if (ns < 2) small_p[ns++] = (const float*)d_in[i]; }
        else                      { if (nb < 2) big_p[nb++]   = (const float*)d_in[i]; }
    }
    const float* outp  = small_p[0];
    const float* tgt   = small_p[1];
    const float* soutp = big_p[0];
    const float* stgt  = big_p[1];

    k0_zero<<<(BINS / 4) / 256, 256>>>();                 // #1

    dim3 b1(32, 8);
    dim3 g1(C_CLASSES / 32, N_ROWS / 32);
    k1_fused<<<g1, b1>>>(outp, tgt, soutp, stgt);         // #2

    kp_all<<<KP_BLOCKS, KP_T>>>();                        // #3 (kpa+kpb+kpc fused)
    k2_rank<<<C_CLASSES / 8, 256>>>();                    // #4  <- profiled launch
    kps_scatter<<<NPWORDS / 256, 256>>>();                // #5
    kc_gaps<<<NI / KC_ILP / 256, 256>>>();                // #6

    ks3_final<<<1, 1024>>>((float*)d_out, out_size);      // #7
}

// round 16
// speedup vs baseline: 1.1266x; 1.0984x over previous
#include <cuda_runtime.h>
#include <cuda_fp16.h>

// ---------------- problem constants ----------------
#define C_CLASSES 8192
#define B_ROWS    256
#define N_ROWS    1280           // B + M*B
#define MAXP      64             // per-class positive cap

#define NI        (B_ROWS * C_CLASSES)   // 2097152 interclass elements
#define LG_BINS   18
#define BINS      (1 << LG_BINS)         // 262144
#define KEY_SHIFT (32 - LG_BINS)         // 14
#define CHUNK     64
#define NCHUNK    (BINS / CHUNK)         // 4096
#define MAXPOS    65536
#define NPWORDS   (NI / 32)              // 65536 posbit words
#define KPA_T     128

// ---------------- scratch (device globals; no allocation allowed) ----------------
__device__ __half   g_tsT[(size_t)C_CLASSES * N_ROWS];  // fp16 perturbed scores (class-major)
__device__ float    g_cpos[(size_t)C_CLASSES * MAXP];   // per-class positive values (fp32)
__device__ int      g_pcnt[C_CLASSES];                  // per-class positive counts
__device__ float    g_prec[C_CLASSES];
__device__ int      g_present[C_CLASSES];

__device__ unsigned g_ikeys[NI];          // interclass order-keys
__device__ unsigned g_iposbit[NPWORDS];   // interclass positive bitmask
__device__ int      g_phist[BINS];        // positive count per bin
__device__ int      g_pexcl[BINS];        // exclusive prefix of g_phist
__device__ int      g_pcursor[BINS];
__device__ int      g_pchunksum[NCHUNK];
__device__ unsigned g_pkeys[MAXPOS];      // positive keys grouped by bin
__device__ int      g_gapneg[MAXPOS + 64];
__device__ int      g_mtotal;

// ---------------- RNG: murmur3 finalizer -> popc-normal (cheap, no MUFU) ----------------
__device__ __forceinline__ float abs_normal(unsigned idx) {
    unsigned h = idx * 0x9E3779B1u;
    h ^= h >> 16; h *= 0x85EBCA6Bu;
    h ^= h >> 13; h *= 0xC2B2AE35u;
    h ^= h >> 16;
    unsigned h2 = h * 0x2545F491u;                              // decorrelate jitter
    float b = (float)(__popc(h) - 16);
    float u = fmaf((float)(h2 >> 8), 5.9604645e-08f, -0.5f);    // [-0.5, 0.5)
    return fabsf((b + u) * 0.35172433f);                         // 1/sqrt(8+1/12)
}

__device__ __forceinline__ unsigned order_key(float v) {
    unsigned u = __float_as_uint(v);
    return (u & 0x80000000u) ? ~u : (u | 0x80000000u);
}

__device__ __forceinline__ float warp_sum_f(float v) {
    #pragma unroll
    for (int off = 16; off; off >>= 1) v += __shfl_xor_sync(0xffffffffu, v, off);
    return v;
}

// ---------------- K0: zero counters (vectorized) ----------------
__global__ __launch_bounds__(256) void k0_zero() {
    int i = blockIdx.x * 256 + threadIdx.x;        // 0..65535
    int4 z = make_int4(0, 0, 0, 0);
    ((int4*)g_phist)[i] = z;                        // BINS/4 = 65536
    if (i < (MAXPOS + 64) / 4) ((int4*)g_gapneg)[i] = z;
    if (i < C_CLASSES / 4)     ((int4*)g_pcnt)[i]   = z;
}

// ---------------- K1: fused perturb+transpose + interclass keys + positive append ----------------
__global__ __launch_bounds__(256) void k1_fused(
    const float* __restrict__ outp, const float* __restrict__ tgt,
    const float* __restrict__ soutp, const float* __restrict__ stgt)
{
    __shared__ float ts_tile[32][33];

    int tx = threadIdx.x;
    int ty = threadIdx.y;
    int c0 = blockIdx.x * 32;
    int r0 = blockIdx.y * 32;
    int cg = c0 + tx;

    #pragma unroll
    for (int j = 0; j < 4; j++) {
        int rl = ty + 8 * j;
        int row = r0 + rl;
        float sc, t;
        if (row < B_ROWS) {
            size_t o = (size_t)row * C_CLASSES + cg;
            sc = outp[o]; t = tgt[o];
        } else {
            size_t o = (size_t)(row - B_ROWS) * C_CLASSES + cg;
            sc = soutp[o]; t = stgt[o];
        }
        unsigned gi = (unsigned)(row * C_CLASSES + cg);
        float an = abs_normal(gi);
        bool pos = (t > 0.5f);
        float v = pos ? (sc - 0.01f * an) : (sc + 0.01f * an);
        ts_tile[rl][tx] = v;

        if (pos) {
            int d = atomicAdd(&g_pcnt[cg], 1);
            if (d < MAXP) g_cpos[(size_t)cg * MAXP + d] = v;
        }

        if (row < B_ROWS) {   // interclass stream: reuse the SAME perturbed value
            unsigned key = order_key(v);
            g_ikeys[row * C_CLASSES + cg] = key;
            unsigned pb = __ballot_sync(0xffffffffu, pos);
            if (tx == 0) g_iposbit[row * (C_CLASSES / 32) + blockIdx.x] = pb;
            if (pos) atomicAdd(&g_phist[key >> KEY_SHIFT], 1);
        }
    }
    __syncthreads();

    #pragma unroll
    for (int rep = 0; rep < 4; rep++) {
        int cl  = ty + 8 * rep;
        int cgg = c0 + cl;
        g_tsT[(size_t)cgg * N_ROWS + r0 + tx] = __float2half(ts_tile[tx][cl]);
    }
}

// ---------------- K2: per-class ranking, packed fp16 compares + precomputed s-ranks ----------------
__global__ __launch_bounds__(256) void k2_rank()
{
    __shared__ float s_pos[8][MAXP];
    __shared__ int   s_rank[8][MAXP];
    int lane = threadIdx.x & 31;
    int wid  = threadIdx.x >> 5;
    int c    = blockIdx.x * 8 + wid;

    const uint4* rowp = (const uint4*)(g_tsT + (size_t)c * N_ROWS);
    uint4 v[5];
    #pragma unroll
    for (int i = 0; i < 5; i++) v[i] = rowp[i * 32 + lane];

    int m = g_pcnt[c];
    int ms = (m < MAXP) ? m : MAXP;
    for (int i = lane; i < ms; i += 32)
        s_pos[wid][i] = g_cpos[(size_t)c * MAXP + i];
    __syncwarp();

    // precompute rank-among-positives once per positive (lane-parallel, integer-exact)
    #pragma unroll
    for (int rr = 0; rr < 2; rr++) {
        int idx = lane + 32 * rr;
        if (idx < ms) {
            float p = s_pos[wid][idx];
            int s = 1;
            for (int jj = 0; jj < ms; jj++) s += (s_pos[wid][jj] > p);
            s_rank[wid][idx] = s;
        }
    }
    __syncwarp();

    float sum = 0.0f;
    for (int kk = 0; kk < ms; kk++) {
        float p = s_pos[wid][kk];
        half2 p2 = __half2half2(__float2half(p));
        half2 c2 = __half2half2(__ushort_as_half(0));
        #pragma unroll
        for (int i = 0; i < 5; i++) {
            c2 = __hadd2(c2, __hgt2(*(const half2*)&v[i].x, p2));
            c2 = __hadd2(c2, __hgt2(*(const half2*)&v[i].y, p2));
            c2 = __hadd2(c2, __hgt2(*(const half2*)&v[i].z, p2));
            c2 = __hadd2(c2, __hgt2(*(const half2*)&v[i].w, p2));
        }
        float cnt = __low2float(c2) + __high2float(c2);
        float r = warp_sum_f(cnt) + 1.0f;
        sum += (float)s_rank[wid][kk] / r;
    }
    if (lane == 0) {
        g_prec[c]    = sum / ((float)m + 1e-5f);
        g_present[c] = (m > 0) ? 1 : 0;
    }
}

// ---------------- KPA: coalesced chunk sums via smem staging ----------------
__global__ __launch_bounds__(KPA_T) void kpa_chunks() {
    __shared__ int sh[KPA_T * 65];
    int t = threadIdx.x;
    int base_bin = blockIdx.x * KPA_T * CHUNK;
    #pragma unroll 8
    for (int i = t; i < KPA_T * CHUNK; i += KPA_T) {
        int c = i >> 6, j = i & 63;
        sh[c * 65 + j] = g_phist[base_bin + i];     // coalesced global read
    }
    __syncthreads();
    int s = 0;
    #pragma unroll 16
    for (int j = 0; j < CHUNK; j++) s += sh[t * 65 + j];
    g_pchunksum[blockIdx.x * KPA_T + t] = s;
}

// ---------------- KPB: single-block scan over chunk sums ----------------
__global__ __launch_bounds__(1024) void kpb_scan() {
    __shared__ int warp_tot[32];
    int t = threadIdx.x;
    int v0[4];
    int s = 0;
    #pragma unroll
    for (int j = 0; j < 4; j++) { v0[j] = g_pchunksum[t * 4 + j]; s += v0[j]; }
    int lane = t & 31, wid = t >> 5;
    int si = s;
    #pragma unroll
    for (int off = 1; off < 32; off <<= 1) {
        int n = __shfl_up_sync(0xffffffffu, si, off);
        if (lane >= off) si += n;
    }
    if (lane == 31) warp_tot[wid] = si;
    __syncthreads();
    if (wid == 0) {
        int w = warp_tot[lane];
        #pragma unroll
        for (int off = 1; off < 32; off <<= 1) {
            int n = __shfl_up_sync(0xffffffffu, w, off);
            if (lane >= off) w += n;
        }
        warp_tot[lane] = w;
    }
    __syncthreads();
    int base = (wid > 0 ? warp_tot[wid - 1] : 0) + si - s;
    int run = base;
    #pragma unroll
    for (int j = 0; j < 4; j++) { g_pchunksum[t * 4 + j] = run; run += v0[j]; }
    if (t == 1023) g_mtotal = run;
}

// ---------------- KPC: coalesced per-bin offsets via smem staging ----------------
__global__ __launch_bounds__(KPA_T) void kpc_offsets() {
    __shared__ int sh[KPA_T * 65];
    int t = threadIdx.x;
    int base_bin = blockIdx.x * KPA_T * CHUNK;
    #pragma unroll 8
    for (int i = t; i < KPA_T * CHUNK; i += KPA_T) {
        int c = i >> 6, j = i & 63;
        sh[c * 65 + j] = g_phist[base_bin + i];
    }
    __syncthreads();
    int run = g_pchunksum[blockIdx.x * KPA_T + t];
    #pragma unroll 16
    for (int j = 0; j < CHUNK; j++) {
        int h = sh[t * 65 + j];
        sh[t * 65 + j] = run;
        run += h;
    }
    __syncthreads();
    #pragma unroll 8
    for (int i = t; i < KPA_T * CHUNK; i += KPA_T) {
        int c = i >> 6, j = i & 63;
        int e = sh[c * 65 + j];
        g_pexcl[base_bin + i]   = e;
        g_pcursor[base_bin + i] = e;
    }
}

// ---------------- scatter positive keys by bin ----------------
__global__ __launch_bounds__(256) void kps_scatter() {
    int w = blockIdx.x * 256 + threadIdx.x;   // 0..NPWORDS-1
    unsigned bits = g_iposbit[w];
    while (bits) {
        int bit = __ffs(bits) - 1;
        bits &= (bits - 1);
        int i = w * 32 + bit;
        unsigned key = g_ikeys[i];
        int b = key >> KEY_SHIFT;
        int d = atomicAdd(&g_pcursor[b], 1);
        g_pkeys[d] = key;
    }
}

// ---------------- KC: per-element gap counting (8-way ILP) ----------------
#define KC_ILP 8
#define KC_THREADS (NI / KC_ILP)   // 262144
__global__ __launch_bounds__(256) void kc_gaps() {
    int tid = blockIdx.x * 256 + threadIdx.x;
    int m = g_mtotal;

    unsigned key[KC_ILP]; unsigned pb[KC_ILP];
    int e0[KC_ILP], pc[KC_ILP];
    #pragma unroll
    for (int u = 0; u < KC_ILP; u++) {
        int i = tid + u * KC_THREADS;
        key[u] = g_ikeys[i];
        pb[u]  = g_iposbit[i >> 5];       // broadcast within warp
    }
    #pragma unroll
    for (int u = 0; u < KC_ILP; u++) {
        int b = key[u] >> KEY_SHIFT;
        e0[u] = g_pexcl[b];
        pc[u] = g_phist[b];
    }
    #pragma unroll
    for (int u = 0; u < KC_ILP; u++) {
        int i = tid + u * KC_THREADS;
        int cgt = 0;
        for (int t = 0; t < pc[u]; t++) cgt += (g_pkeys[e0[u] + t] > key[u]);
        int j = (m - e0[u] - pc[u]) + cgt;   // # positives > this element
        bool pos = (pb[u] >> (i & 31)) & 1u;
        if (!pos) atomicAdd(&g_gapneg[j], 1);
    }
}

// ---------------- KS3: gap scan + interclass terms + final combine ----------------
__global__ __launch_bounds__(1024) void ks3_final(float* __restrict__ out, int out_size)
{
    __shared__ int wtot[32];
    __shared__ double wsumd[32];
    __shared__ int wsumi[32];
    int t = threadIdx.x;
    int lane = t & 31, wid = t >> 5;
    int m = g_mtotal;

    int carry = 0;
    double acc = 0.0;
    for (int base = 0; base < m; base += 1024) {
        int i = base + t;
        int g = (i < m) ? g_gapneg[i] : 0;
        int si = g;
        #pragma unroll
        for (int off = 1; off < 32; off <<= 1) {
            int n = __shfl_up_sync(0xffffffffu, si, off);
            if (lane >= off) si += n;
        }
        if (lane == 31) wtot[wid] = si;
        __syncthreads();
        if (wid == 0) {
            int w = wtot[lane];
            #pragma unroll
            for (int off = 1; off < 32; off <<= 1) {
                int n = __shfl_up_sync(0xffffffffu, w, off);
                if (lane >= off) w += n;
            }
            wtot[lane] = w;
        }
        __syncthreads();
        int P = (wid > 0 ? wtot[wid - 1] : 0) + si;
        if (i < m) {
            int r = 1 + i + carry + P;
            acc += (double)(i + 1) / (double)r;
        }
        carry += wtot[31];
        __syncthreads();
    }
    #pragma unroll
    for (int off = 16; off; off >>= 1) acc += __shfl_xor_sync(0xffffffffu, acc, off);
    if (lane == 0) wsumd[wid] = acc;
    __syncthreads();
    double isum = 0.0;
    if (t == 0) {
        #pragma unroll
        for (int i = 0; i < 32; i++) isum += wsumd[i];
    }
    __syncthreads();

    double ps = 0.0; int pr = 0;
    for (int i = t; i < C_CLASSES; i += 1024) { ps += (double)g_prec[i]; pr += g_present[i]; }
    #pragma unroll
    for (int off = 16; off; off >>= 1) {
        ps += __shfl_xor_sync(0xffffffffu, ps, off);
        pr += __shfl_xor_sync(0xffffffffu, pr, off);
    }
    if (lane == 0) { wsumd[wid] = ps; wsumi[wid] = pr; }
    __syncthreads();
    if (t == 0) {
        double pst = 0.0; int prt = 0;
        #pragma unroll
        for (int i = 0; i < 32; i++) { pst += wsumd[i]; prt += wsumi[i]; }
        int denom = (prt > 0) ? prt : 1;
        float cross = 1.0f - (float)(pst / (double)denom);
        float inter = (m > 0) ? (1.0f - (float)(isum / ((double)m + 1e-5))) : 1.0f;
        float loss = 0.5f * cross + 0.5f * inter;
        for (int j = 0; j < out_size; j++) out[j] = loss;
    }
}

// ---------------- launch (fork-join graph: k2 overlaps the interclass branch) ----------------
extern "C" void kernel_launch(void* const* d_in, const int* in_sizes, int n_in,
                              void* d_out, int out_size)
{
    const int SMALL = B_ROWS * C_CLASSES;
    const float* small_p[2] = {nullptr, nullptr};
    const float* big_p[2]   = {nullptr, nullptr};
    int ns = 0, nb = 0;
    for (int i = 0; i < n_in; i++) {
        if (in_sizes[i] == SMALL) { if (ns < 2) small_p[ns++] = (const float*)d_in[i]; }
        else                      { if (nb < 2) big_p[nb++]   = (const float*)d_in[i]; }
    }
    const float* outp  = small_p[0];
    const float* tgt   = small_p[1];
    const float* soutp = big_p[0];
    const float* stgt  = big_p[1];

    // one-time resource init (no device memory involved)
    static cudaStream_t s2 = nullptr;
    static cudaEvent_t evA = nullptr, evB = nullptr;
    if (s2 == nullptr) {
        cudaStreamCreateWithFlags(&s2, cudaStreamNonBlocking);
        cudaEventCreateWithFlags(&evA, cudaEventDisableTiming);
        cudaEventCreateWithFlags(&evB, cudaEventDisableTiming);
    }

    k0_zero<<<(BINS / 4) / 256, 256>>>();

    dim3 b1(32, 8);
    dim3 g1(C_CLASSES / 32, N_ROWS / 32);
    k1_fused<<<g1, b1>>>(outp, tgt, soutp, stgt);

    // fork: k2 on side stream, interclass pipeline on main stream
    cudaEventRecord(evA, 0);
    cudaStreamWaitEvent(s2, evA, 0);
    k2_rank<<<C_CLASSES / 8, 256, 0, s2>>>();

    kpa_chunks<<<NCHUNK / KPA_T, KPA_T>>>();
    kpb_scan<<<1, 1024>>>();
    kpc_offsets<<<NCHUNK / KPA_T, KPA_T>>>();
    kps_scatter<<<NPWORDS / 256, 256>>>();
    kc_gaps<<<NI / KC_ILP / 256, 256>>>();

    // join
    cudaEventRecord(evB, s2);
    cudaStreamWaitEvent(0, evB, 0);

    ks3_final<<<1, 1024>>>((float*)d_out, out_size);
}

// round 17
// speedup vs baseline: 1.1541x; 1.0244x over previous
#include <cuda_runtime.h>
#include <cuda_fp16.h>

// ---------------- problem constants ----------------
#define C_CLASSES 8192
#define B_ROWS    256
#define N_ROWS    1280           // B + M*B
#define MAXP      64             // per-class positive cap

#define NI        (B_ROWS * C_CLASSES)   // 2097152 interclass elements
#define LG_BINS   18
#define BINS      (1 << LG_BINS)         // 262144
#define KEY_SHIFT (32 - LG_BINS)         // 14
#define CHUNK     64
#define NCHUNK    (BINS / CHUNK)         // 4096
#define MAXPOS    65536
#define NPWORDS   (NI / 32)              // 65536 posbit words
#define KPA_T     128

// ---------------- scratch (device globals; no allocation allowed) ----------------
__device__ __half   g_tsT[(size_t)C_CLASSES * N_ROWS];  // fp16 perturbed scores (class-major)
__device__ float    g_cpos[(size_t)C_CLASSES * MAXP];   // per-class positive values (fp32)
__device__ int      g_pcnt[C_CLASSES];                  // per-class positive counts
__device__ float    g_prec[C_CLASSES];
__device__ int      g_present[C_CLASSES];

__device__ unsigned g_ikeys[NI];          // interclass order-keys
__device__ unsigned g_iposbit[NPWORDS];   // interclass positive bitmask
__device__ int      g_phist[BINS];        // positive count per bin
__device__ int      g_pexcl[BINS];        // exclusive prefix of g_phist
__device__ int      g_pcursor[BINS];
__device__ int      g_pchunksum[NCHUNK];
__device__ unsigned g_pkeys[MAXPOS];      // positive keys grouped by bin
__device__ int      g_gapneg[MAXPOS + 64];
__device__ int      g_mtotal;

// ---------------- RNG: murmur3 finalizer -> popc-normal (cheap, no MUFU) ----------------
__device__ __forceinline__ float abs_normal(unsigned idx) {
    unsigned h = idx * 0x9E3779B1u;
    h ^= h >> 16; h *= 0x85EBCA6Bu;
    h ^= h >> 13; h *= 0xC2B2AE35u;
    h ^= h >> 16;
    unsigned h2 = h * 0x2545F491u;                              // decorrelate jitter
    float b = (float)(__popc(h) - 16);
    float u = fmaf((float)(h2 >> 8), 5.9604645e-08f, -0.5f);    // [-0.5, 0.5)
    return fabsf((b + u) * 0.35172433f);                         // 1/sqrt(8+1/12)
}

__device__ __forceinline__ unsigned order_key(float v) {
    unsigned u = __float_as_uint(v);
    return (u & 0x80000000u) ? ~u : (u | 0x80000000u);
}

__device__ __forceinline__ float warp_sum_f(float v) {
    #pragma unroll
    for (int off = 16; off; off >>= 1) v += __shfl_xor_sync(0xffffffffu, v, off);
    return v;
}

// ---------------- K0: zero counters (vectorized) ----------------
__global__ __launch_bounds__(256) void k0_zero() {
    int i = blockIdx.x * 256 + threadIdx.x;        // 0..65535
    int4 z = make_int4(0, 0, 0, 0);
    ((int4*)g_phist)[i] = z;                        // BINS/4 = 65536
    if (i < (MAXPOS + 64) / 4) ((int4*)g_gapneg)[i] = z;
    if (i < C_CLASSES / 4)     ((int4*)g_pcnt)[i]   = z;
}

// ---------------- K1: perturb+transpose (+ interclass emit for rows<256) ----------------
// rbase: starting row tile (0 for k1a covering rows 0..255, 8 for k1b covering 256..1279)
__global__ __launch_bounds__(256) void k1_fused(
    const float* __restrict__ outp, const float* __restrict__ tgt,
    const float* __restrict__ soutp, const float* __restrict__ stgt, int rbase)
{
    __shared__ float ts_tile[32][33];

    int tx = threadIdx.x;
    int ty = threadIdx.y;
    int c0 = blockIdx.x * 32;
    int r0 = (blockIdx.y + rbase) * 32;
    int cg = c0 + tx;

    #pragma unroll
    for (int j = 0; j < 4; j++) {
        int rl = ty + 8 * j;
        int row = r0 + rl;
        float sc, t;
        if (row < B_ROWS) {
            size_t o = (size_t)row * C_CLASSES + cg;
            sc = outp[o]; t = tgt[o];
        } else {
            size_t o = (size_t)(row - B_ROWS) * C_CLASSES + cg;
            sc = soutp[o]; t = stgt[o];
        }
        unsigned gi = (unsigned)(row * C_CLASSES + cg);
        float an = abs_normal(gi);
        bool pos = (t > 0.5f);
        float v = pos ? (sc - 0.01f * an) : (sc + 0.01f * an);
        ts_tile[rl][tx] = v;

        if (pos) {
            int d = atomicAdd(&g_pcnt[cg], 1);
            if (d < MAXP) g_cpos[(size_t)cg * MAXP + d] = v;
        }

        if (row < B_ROWS) {   // interclass stream: reuse the SAME perturbed value
            unsigned key = order_key(v);
            g_ikeys[row * C_CLASSES + cg] = key;
            unsigned pb = __ballot_sync(0xffffffffu, pos);
            if (tx == 0) g_iposbit[row * (C_CLASSES / 32) + blockIdx.x] = pb;
            if (pos) atomicAdd(&g_phist[key >> KEY_SHIFT], 1);
        }
    }
    __syncthreads();

    #pragma unroll
    for (int rep = 0; rep < 4; rep++) {
        int cl  = ty + 8 * rep;
        int cgg = c0 + cl;
        g_tsT[(size_t)cgg * N_ROWS + r0 + tx] = __float2half(ts_tile[tx][cl]);
    }
}

// ---------------- K2: per-class ranking, packed fp16 compares + precomputed s-ranks ----------------
__global__ __launch_bounds__(256) void k2_rank()
{
    __shared__ float s_pos[8][MAXP];
    __shared__ int   s_rank[8][MAXP];
    int lane = threadIdx.x & 31;
    int wid  = threadIdx.x >> 5;
    int c    = blockIdx.x * 8 + wid;

    const uint4* rowp = (const uint4*)(g_tsT + (size_t)c * N_ROWS);
    uint4 v[5];
    #pragma unroll
    for (int i = 0; i < 5; i++) v[i] = rowp[i * 32 + lane];

    int m = g_pcnt[c];
    int ms = (m < MAXP) ? m : MAXP;
    for (int i = lane; i < ms; i += 32)
        s_pos[wid][i] = g_cpos[(size_t)c * MAXP + i];
    __syncwarp();

    // precompute rank-among-positives (lane-parallel, integer-exact)
    #pragma unroll
    for (int rr = 0; rr < 2; rr++) {
        int idx = lane + 32 * rr;
        if (idx < ms) {
            float p = s_pos[wid][idx];
            int s = 1;
            for (int jj = 0; jj < ms; jj++) s += (s_pos[wid][jj] > p);
            s_rank[wid][idx] = s;
        }
    }
    __syncwarp();

    float sum = 0.0f;
    for (int kk = 0; kk < ms; kk++) {
        float p = s_pos[wid][kk];
        half2 p2 = __half2half2(__float2half(p));
        half2 c2 = __half2half2(__ushort_as_half(0));
        #pragma unroll
        for (int i = 0; i < 5; i++) {
            c2 = __hadd2(c2, __hgt2(*(const half2*)&v[i].x, p2));
            c2 = __hadd2(c2, __hgt2(*(const half2*)&v[i].y, p2));
            c2 = __hadd2(c2, __hgt2(*(const half2*)&v[i].z, p2));
            c2 = __hadd2(c2, __hgt2(*(const half2*)&v[i].w, p2));
        }
        float cnt = __low2float(c2) + __high2float(c2);
        float r = warp_sum_f(cnt) + 1.0f;
        sum += (float)s_rank[wid][kk] / r;
    }
    if (lane == 0) {
        g_prec[c]    = sum / ((float)m + 1e-5f);
        g_present[c] = (m > 0) ? 1 : 0;
    }
}

// ---------------- KPA: coalesced chunk sums via smem staging ----------------
__global__ __launch_bounds__(KPA_T) void kpa_chunks() {
    __shared__ int sh[KPA_T * 65];
    int t = threadIdx.x;
    int base_bin = blockIdx.x * KPA_T * CHUNK;
    #pragma unroll 8
    for (int i = t; i < KPA_T * CHUNK; i += KPA_T) {
        int c = i >> 6, j = i & 63;
        sh[c * 65 + j] = g_phist[base_bin + i];     // coalesced global read
    }
    __syncthreads();
    int s = 0;
    #pragma unroll 16
    for (int j = 0; j < CHUNK; j++) s += sh[t * 65 + j];
    g_pchunksum[blockIdx.x * KPA_T + t] = s;
}

// ---------------- KPB: single-block scan over chunk sums ----------------
__global__ __launch_bounds__(1024) void kpb_scan() {
    __shared__ int warp_tot[32];
    int t = threadIdx.x;
    int v0[4];
    int s = 0;
    #pragma unroll
    for (int j = 0; j < 4; j++) { v0[j] = g_pchunksum[t * 4 + j]; s += v0[j]; }
    int lane = t & 31, wid = t >> 5;
    int si = s;
    #pragma unroll
    for (int off = 1; off < 32; off <<= 1) {
        int n = __shfl_up_sync(0xffffffffu, si, off);
        if (lane >= off) si += n;
    }
    if (lane == 31) warp_tot[wid] = si;
    __syncthreads();
    if (wid == 0) {
        int w = warp_tot[lane];
        #pragma unroll
        for (int off = 1; off < 32; off <<= 1) {
            int n = __shfl_up_sync(0xffffffffu, w, off);
            if (lane >= off) w += n;
        }
        warp_tot[lane] = w;
    }
    __syncthreads();
    int base = (wid > 0 ? warp_tot[wid - 1] : 0) + si - s;
    int run = base;
    #pragma unroll
    for (int j = 0; j < 4; j++) { g_pchunksum[t * 4 + j] = run; run += v0[j]; }
    if (t == 1023) g_mtotal = run;
}

// ---------------- KPC: coalesced per-bin offsets via smem staging ----------------
__global__ __launch_bounds__(KPA_T) void kpc_offsets() {
    __shared__ int sh[KPA_T * 65];
    int t = threadIdx.x;
    int base_bin = blockIdx.x * KPA_T * CHUNK;
    #pragma unroll 8
    for (int i = t; i < KPA_T * CHUNK; i += KPA_T) {
        int c = i >> 6, j = i & 63;
        sh[c * 65 + j] = g_phist[base_bin + i];
    }
    __syncthreads();
    int run = g_pchunksum[blockIdx.x * KPA_T + t];
    #pragma unroll 16
    for (int j = 0; j < CHUNK; j++) {
        int h = sh[t * 65 + j];
        sh[t * 65 + j] = run;
        run += h;
    }
    __syncthreads();
    #pragma unroll 8
    for (int i = t; i < KPA_T * CHUNK; i += KPA_T) {
        int c = i >> 6, j = i & 63;
        int e = sh[c * 65 + j];
        g_pexcl[base_bin + i]   = e;
        g_pcursor[base_bin + i] = e;
    }
}

// ---------------- scatter positive keys by bin ----------------
__global__ __launch_bounds__(256) void kps_scatter() {
    int w = blockIdx.x * 256 + threadIdx.x;   // 0..NPWORDS-1
    unsigned bits = g_iposbit[w];
    while (bits) {
        int bit = __ffs(bits) - 1;
        bits &= (bits - 1);
        int i = w * 32 + bit;
        unsigned key = g_ikeys[i];
        int b = key >> KEY_SHIFT;
        int d = atomicAdd(&g_pcursor[b], 1);
        g_pkeys[d] = key;
    }
}

// ---------------- KC: per-element gap counting (8-way ILP) ----------------
#define KC_ILP 8
#define KC_THREADS (NI / KC_ILP)   // 262144
__global__ __launch_bounds__(256) void kc_gaps() {
    int tid = blockIdx.x * 256 + threadIdx.x;
    int m = g_mtotal;

    unsigned key[KC_ILP]; unsigned pb[KC_ILP];
    int e0[KC_ILP], pc[KC_ILP];
    #pragma unroll
    for (int u = 0; u < KC_ILP; u++) {
        int i = tid + u * KC_THREADS;
        key[u] = g_ikeys[i];
        pb[u]  = g_iposbit[i >> 5];       // broadcast within warp
    }
    #pragma unroll
    for (int u = 0; u < KC_ILP; u++) {
        int b = key[u] >> KEY_SHIFT;
        e0[u] = g_pexcl[b];
        pc[u] = g_phist[b];
    }
    #pragma unroll
    for (int u = 0; u < KC_ILP; u++) {
        int i = tid + u * KC_THREADS;
        int cgt = 0;
        for (int t = 0; t < pc[u]; t++) cgt += (g_pkeys[e0[u] + t] > key[u]);
        int j = (m - e0[u] - pc[u]) + cgt;   // # positives > this element
        bool pos = (pb[u] >> (i & 31)) & 1u;
        if (!pos) atomicAdd(&g_gapneg[j], 1);
    }
}

// ---------------- KS3: gap scan + interclass terms + final combine ----------------
__global__ __launch_bounds__(1024) void ks3_final(float* __restrict__ out, int out_size)
{
    __shared__ int wtot[32];
    __shared__ double wsumd[32];
    __shared__ int wsumi[32];
    int t = threadIdx.x;
    int lane = t & 31, wid = t >> 5;
    int m = g_mtotal;

    int carry = 0;
    double acc = 0.0;
    for (int base = 0; base < m; base += 1024) {
        int i = base + t;
        int g = (i < m) ? g_gapneg[i] : 0;
        int si = g;
        #pragma unroll
        for (int off = 1; off < 32; off <<= 1) {
            int n = __shfl_up_sync(0xffffffffu, si, off);
            if (lane >= off) si += n;
        }
        if (lane == 31) wtot[wid] = si;
        __syncthreads();
        if (wid == 0) {
            int w = wtot[lane];
            #pragma unroll
            for (int off = 1; off < 32; off <<= 1) {
                int n = __shfl_up_sync(0xffffffffu, w, off);
                if (lane >= off) w += n;
            }
            wtot[lane] = w;
        }
        __syncthreads();
        int P = (wid > 0 ? wtot[wid - 1] : 0) + si;
        if (i < m) {
            int r = 1 + i + carry + P;
            acc += (double)(i + 1) / (double)r;
        }
        carry += wtot[31];
        __syncthreads();
    }
    #pragma unroll
    for (int off = 16; off; off >>= 1) acc += __shfl_xor_sync(0xffffffffu, acc, off);
    if (lane == 0) wsumd[wid] = acc;
    __syncthreads();
    double isum = 0.0;
    if (t == 0) {
        #pragma unroll
        for (int i = 0; i < 32; i++) isum += wsumd[i];
    }
    __syncthreads();

    double ps = 0.0; int pr = 0;
    for (int i = t; i < C_CLASSES; i += 1024) { ps += (double)g_prec[i]; pr += g_present[i]; }
    #pragma unroll
    for (int off = 16; off; off >>= 1) {
        ps += __shfl_xor_sync(0xffffffffu, ps, off);
        pr += __shfl_xor_sync(0xffffffffu, pr, off);
    }
    if (lane == 0) { wsumd[wid] = ps; wsumi[wid] = pr; }
    __syncthreads();
    if (t == 0) {
        double pst = 0.0; int prt = 0;
        #pragma unroll
        for (int i = 0; i < 32; i++) { pst += wsumd[i]; prt += wsumi[i]; }
        int denom = (prt > 0) ? prt : 1;
        float cross = 1.0f - (float)(pst / (double)denom);
        float inter = (m > 0) ? (1.0f - (float)(isum / ((double)m + 1e-5))) : 1.0f;
        float loss = 0.5f * cross + 0.5f * inter;
        for (int j = 0; j < out_size; j++) out[j] = loss;
    }
}

// ---------------- launch: two-level fork-join graph ----------------
extern "C" void kernel_launch(void* const* d_in, const int* in_sizes, int n_in,
                              void* d_out, int out_size)
{
    const int SMALL = B_ROWS * C_CLASSES;
    const float* small_p[2] = {nullptr, nullptr};
    const float* big_p[2]   = {nullptr, nullptr};
    int ns = 0, nb = 0;
    for (int i = 0; i < n_in; i++) {
        if (in_sizes[i] == SMALL) { if (ns < 2) small_p[ns++] = (const float*)d_in[i]; }
        else                      { if (nb < 2) big_p[nb++]   = (const float*)d_in[i]; }
    }
    const float* outp  = small_p[0];
    const float* tgt   = small_p[1];
    const float* soutp = big_p[0];
    const float* stgt  = big_p[1];

    // one-time resource init (no device memory involved)
    static cudaStream_t s2 = nullptr;
    static cudaEvent_t ev0 = nullptr, evA = nullptr, evB = nullptr;
    if (s2 == nullptr) {
        cudaStreamCreateWithFlags(&s2, cudaStreamNonBlocking);
        cudaEventCreateWithFlags(&ev0, cudaEventDisableTiming);
        cudaEventCreateWithFlags(&evA, cudaEventDisableTiming);
        cudaEventCreateWithFlags(&evB, cudaEventDisableTiming);
    }

    k0_zero<<<(BINS / 4) / 256, 256>>>();
    cudaEventRecord(ev0, 0);
    cudaStreamWaitEvent(s2, ev0, 0);

    dim3 b1(32, 8);
    // k1a: rows 0..255 (interclass emit) on main stream
    k1_fused<<<dim3(C_CLASSES / 32, B_ROWS / 32), b1>>>(outp, tgt, soutp, stgt, 0);
    // k1b: rows 256..1279 on side stream (concurrent with k1a + early chain)
    k1_fused<<<dim3(C_CLASSES / 32, (N_ROWS - B_ROWS) / 32), b1, 0, s2>>>(outp, tgt, soutp, stgt, B_ROWS / 32);

    cudaEventRecord(evA, 0);   // after k1a

    // interclass chain on main (needs only k1a)
    kpa_chunks<<<NCHUNK / KPA_T, KPA_T>>>();
    kpb_scan<<<1, 1024>>>();
    kpc_offsets<<<NCHUNK / KPA_T, KPA_T>>>();
    kps_scatter<<<NPWORDS / 256, 256>>>();
    kc_gaps<<<NI / KC_ILP / 256, 256>>>();

    // k2 on side stream after k1b (program order) AND k1a (event)
    cudaStreamWaitEvent(s2, evA, 0);
    k2_rank<<<C_CLASSES / 8, 256, 0, s2>>>();

    // join
    cudaEventRecord(evB, s2);
    cudaStreamWaitEvent(0, evB, 0);

    ks3_final<<<1, 1024>>>((float*)d_out, out_size);
}